// round 7
// baseline (speedup 1.0000x reference)
#include <cuda_runtime.h>
#include <math.h>
#include <stdint.h>

// output [B=2, C=8, H=128, W=128, D=128] fp32.
// t = where(x > 0.5, x, 0); per-(b,c): s = sum t, sy = sum t*(h/H), sx, sz analog.
// centroids = s?/s; loss = sum over 8 relations of mean_b((diff - gt)^2), nan/inf->0.
//
// TMA-path version: per block, a 2-stage 16KB SMEM ring filled by
// cp.async.bulk (elected thread), consumed by all 256 threads from SMEM.
// grid = 592 = 4 * 148 (one balanced wave), 37 blocks/channel, 13-14 units each.

#define NCH          16
#define UNITS_PER_CH 512
#define BLK_PER_CH   37
#define NBLOCKS      (NCH * BLK_PER_CH)   // 592
#define THREADS      256
#define UNIT_VEC     1024                  // float4 per unit (16 KiB)
#define UNIT_BYTES   16384
#define NSTAGES      2

__device__ float g_partials[NBLOCKS * 4];   // per block: {s, sy, sx, sz}
__device__ int   g_count = 0;

__constant__ int   c_rel_i[8] = {0, 1, 2, 3, 4, 5, 6, 0};
__constant__ int   c_rel_j[8] = {1, 2, 3, 4, 5, 6, 7, 7};
__constant__ float c_gt_y[8]  = { 0.1f,  0.0f, -0.1f,  0.0f,  0.05f,  0.0f, 0.1f, -0.05f};
__constant__ float c_gt_x[8]  = { 0.0f,  0.1f,  0.05f, 0.0f, -0.05f,  0.1f, 0.0f,  0.05f};
__constant__ float c_gt_z[8]  = { 0.05f, 0.0f,  0.0f,  0.1f,  0.0f, -0.1f, 0.0f,  0.05f};

__device__ __forceinline__ float nan0(float x) { return isfinite(x) ? x : 0.f; }

__device__ __forceinline__ uint32_t smem_u32(const void* p) {
    uint32_t a;
    asm("{ .reg .u64 t; cvta.to.shared.u64 t, %1; cvt.u32.u64 %0, t; }" : "=r"(a) : "l"(p));
    return a;
}

__device__ __forceinline__ void mbar_init(uint32_t addr, uint32_t count) {
    asm volatile("mbarrier.init.shared.b64 [%0], %1;" :: "r"(addr), "r"(count) : "memory");
}

__device__ __forceinline__ void mbar_arrive(uint32_t addr) {
    asm volatile("mbarrier.arrive.release.cta.shared::cta.b64 _, [%0];" :: "r"(addr) : "memory");
}

__device__ __forceinline__ void mbar_expect_tx(uint32_t addr, uint32_t bytes) {
    asm volatile("mbarrier.arrive.expect_tx.shared.b64 _, [%0], %1;"
                 :: "r"(addr), "r"(bytes) : "memory");
}

__device__ __forceinline__ void mbar_wait(uint32_t addr, uint32_t parity) {
    asm volatile(
        "{\n\t.reg .pred P;\n"
        "W_%=:\n\t"
        "mbarrier.try_wait.parity.acquire.cta.shared::cta.b64 P, [%0], %1, 0x989680;\n\t"
        "@!P bra W_%=;\n\t}"
        :: "r"(addr), "r"(parity) : "memory");
}

__device__ __forceinline__ void bulk_copy_g2s(uint32_t dst_smem, const void* src,
                                              uint32_t bytes, uint32_t mbar) {
    asm volatile(
        "cp.async.bulk.shared::cluster.global.mbarrier::complete_tx::bytes [%0], [%1], %2, [%3];"
        :: "r"(dst_smem), "l"(src), "r"(bytes), "r"(mbar) : "memory");
}

__global__ void __launch_bounds__(THREADS)
gsl_fused_kernel(const float* __restrict__ in, float* __restrict__ out, int out_size) {
    __shared__ __align__(16) float4 tiles[NSTAGES][UNIT_VEC];   // 32 KiB
    __shared__ __align__(8)  uint64_t bars[2 * NSTAGES];        // full[0..1], empty[2..3]

    const int tid  = threadIdx.x;
    const float inv = 1.0f / 128.0f;

    const int ch = blockIdx.x / BLK_PER_CH;
    const int g  = blockIdx.x - ch * BLK_PER_CH;        // 0..36
    const int nu = (UNITS_PER_CH - g + BLK_PER_CH - 1) / BLK_PER_CH;  // 13 or 14

    const float* chbase = in + (size_t)ch * (UNITS_PER_CH * (size_t)UNIT_VEC * 4);

    const uint32_t full0  = smem_u32(&bars[0]);
    const uint32_t empty0 = smem_u32(&bars[NSTAGES]);
    const uint32_t tile0  = smem_u32(&tiles[0][0]);

    if (tid == 0) {
        mbar_init(full0,      1);       mbar_init(full0 + 8,      1);
        mbar_init(empty0,     THREADS); mbar_init(empty0 + 8,     THREADS);
    }
    __syncthreads();

    // thread-constant z weights: z = (tid & 31) * 4
    const float cz0 = (float)((tid & 31) << 2) * inv;
    const float w0 = cz0, w1 = cz0 + inv, w2 = cz0 + 2.f * inv, w3 = cz0 + 3.f * inv;
    const float cx0 = (float)(tid >> 5) * inv;

    float s = 0.f, sy = 0.f, sx = 0.f, sz = 0.f;

    // prologue: issue fill f=0
    if (tid == 0) {
        // fill f: stage f&1, empty-use n=f>>1, wait parity = ((f>>1)&1)^1
        mbar_wait(empty0, 1);                          // fresh -> passes
        mbar_expect_tx(full0, UNIT_BYTES);
        bulk_copy_g2s(tile0, chbase + (size_t)g * (UNIT_VEC * 4), UNIT_BYTES, full0);
    }

    int u = g;
    for (int k = 0; k < nu; ++k) {
        const int st = k & 1;

        // producer: issue fill for k+1 into the other stage
        if (tid == 0 && k + 1 < nu) {
            const int f = k + 1;
            const int so = (f & 1) * 8;
            mbar_wait(empty0 + so, (((f >> 1) & 1) ^ 1));
            mbar_expect_tx(full0 + so, UNIT_BYTES);
            bulk_copy_g2s(tile0 + (f & 1) * UNIT_BYTES,
                          chbase + (size_t)(u + BLK_PER_CH) * (UNIT_VEC * 4),
                          UNIT_BYTES, full0 + so);
        }

        // consumers: wait tile k
        mbar_wait(full0 + st * 8, (k >> 1) & 1);

        const float cy  = (float)((u >> 2) & 127) * inv;
        const float cxb = cx0 + (float)((u & 3) << 5) * inv;

        float sb = 0.f;
        #pragma unroll
        for (int q = 0; q < 4; ++q) {
            float4 v = tiles[st][tid + 256 * q];
            const float cx = cxb + (float)(q * 8) * inv;

            float t0 = v.x > 0.5f ? v.x : 0.f;
            float t1 = v.y > 0.5f ? v.y : 0.f;
            float t2 = v.z > 0.5f ? v.z : 0.f;
            float t3 = v.w > 0.5f ? v.w : 0.f;

            float ts = (t0 + t1) + (t2 + t3);
            sb += ts;
            sx = fmaf(ts, cx, sx);
            sz = fmaf(t0, w0, fmaf(t1, w1, fmaf(t2, w2, fmaf(t3, w3, sz))));
        }
        s += sb;
        sy = fmaf(sb, cy, sy);

        mbar_arrive(empty0 + st * 8);   // stage free for reuse
        u += BLK_PER_CH;
    }

    // block reduce (s, sy, sx, sz)
    #pragma unroll
    for (int off = 16; off > 0; off >>= 1) {
        s  += __shfl_down_sync(0xFFFFFFFFu, s,  off);
        sy += __shfl_down_sync(0xFFFFFFFFu, sy, off);
        sx += __shfl_down_sync(0xFFFFFFFFu, sx, off);
        sz += __shfl_down_sync(0xFFFFFFFFu, sz, off);
    }

    __shared__ float sh[THREADS / 32][4];
    const int lane = tid & 31;
    const int wid  = tid >> 5;
    if (lane == 0) { sh[wid][0] = s; sh[wid][1] = sy; sh[wid][2] = sx; sh[wid][3] = sz; }
    __syncthreads();

    __shared__ bool is_last;
    if (wid == 0) {
        float a = (lane < THREADS / 32) ? sh[lane][0] : 0.f;
        float b = (lane < THREADS / 32) ? sh[lane][1] : 0.f;
        float c = (lane < THREADS / 32) ? sh[lane][2] : 0.f;
        float d = (lane < THREADS / 32) ? sh[lane][3] : 0.f;
        #pragma unroll
        for (int off = 4; off > 0; off >>= 1) {
            a += __shfl_down_sync(0xFFFFFFFFu, a, off);
            b += __shfl_down_sync(0xFFFFFFFFu, b, off);
            c += __shfl_down_sync(0xFFFFFFFFu, c, off);
            d += __shfl_down_sync(0xFFFFFFFFu, d, off);
        }
        if (lane == 0) {
            float4 pp; pp.x = a; pp.y = b; pp.z = c; pp.w = d;
            reinterpret_cast<float4*>(g_partials)[blockIdx.x] = pp;
            __threadfence();
            int prev = atomicAdd(&g_count, 1);
            is_last = (prev == NBLOCKS - 1);
        }
    }
    __syncthreads();

    if (!is_last) return;

    // ---- final reduction: this block only ----
    __shared__ float cen_y[NCH], cen_x[NCH], cen_z[NCH];

    for (int c = wid; c < NCH; c += THREADS / 32) {
        const int base = c * BLK_PER_CH;
        volatile const float* p0 = &g_partials[(base + lane) * 4];
        float a = p0[0], b = p0[1], cc = p0[2], d = p0[3];
        if (lane < BLK_PER_CH - 32) {
            volatile const float* p1 = &g_partials[(base + 32 + lane) * 4];
            a += p1[0]; b += p1[1]; cc += p1[2]; d += p1[3];
        }
        #pragma unroll
        for (int off = 16; off > 0; off >>= 1) {
            a  += __shfl_down_sync(0xFFFFFFFFu, a,  off);
            b  += __shfl_down_sync(0xFFFFFFFFu, b,  off);
            cc += __shfl_down_sync(0xFFFFFFFFu, cc, off);
            d  += __shfl_down_sync(0xFFFFFFFFu, d,  off);
        }
        if (lane == 0) {
            cen_y[c] = b / a;
            cen_x[c] = cc / a;
            cen_z[c] = d / a;
        }
    }
    __syncthreads();

    if (tid == 0) {
        float loss = 0.f;
        #pragma unroll
        for (int r = 0; r < 8; r++) {
            int ci = c_rel_i[r], cj = c_rel_j[r];
            float my = 0.f, mx = 0.f, mz = 0.f;
            #pragma unroll
            for (int b = 0; b < 2; b++) {
                int ii = b * 8 + ci, jj = b * 8 + cj;
                float dy = nan0(cen_y[ii] - cen_y[jj] - c_gt_y[r]);
                float dx = nan0(cen_x[ii] - cen_x[jj] - c_gt_x[r]);
                float dz = nan0(cen_z[ii] - cen_z[jj] - c_gt_z[r]);
                my += dy * dy; mx += dx * dx; mz += dz * dz;
            }
            loss += 0.5f * (my + mx + mz);   // mean over B=2
        }
        out[0] = loss;
        g_count = 0;                          // reset for next graph replay
    }
    for (int i = 1 + tid; i < out_size; i += THREADS) out[i] = 0.f;
}

extern "C" void kernel_launch(void* const* d_in, const int* in_sizes, int n_in,
                              void* d_out, int out_size) {
    const float* in = (const float*)d_in[0];
    gsl_fused_kernel<<<NBLOCKS, THREADS>>>(in, (float*)d_out, out_size);
}